// round 15
// baseline (speedup 1.0000x reference)
#include <cuda_runtime.h>
#include <math.h>
#include <stdint.h>

#define BATCH 512
#define SEQ   80
#define NV    36
#define NC    16
#define ANGLE 128
#define EMB   64
#define HID   512
#define FEAT  2176
#define INDIM 2240
#define GATES 2048
#define FEAT4 544

// ---------------- scratch ----------------
#define O_TDENSE 0u
#define O_TFEAT  1114112u
#define O_XV     2228224u
#define O_XO     3375104u
#define O_GV     4521984u
#define O_GO     5570560u
#define O_HCV    6619136u
#define O_HCO    7143424u
#define O_TAVV   7667712u
#define O_TAVO   7929856u
#define O_HC2    8192000u
#define O_TCAND  8716288u
#define P_ACC    9830400u                   // 3072 * 2176 = 6684672 floats
#define P_MD     16515072u                  // 3072 * 2
#define SCRATCH_FLOATS 16521216u
__device__ float g_scratch[SCRATCH_FLOATS];

#define OFF_H1V   0u
#define OFF_H1O   262144u
#define OFF_C1V   524288u
#define OFF_C1O   786432u
#define OFF_LOGIT 1048576u
#define OFF_HTV   1056768u
#define OFF_HTO   1318912u

// ==================== helpers ====================
__device__ __forceinline__ uint32_t smem_u32(const void* p) {
    uint32_t a;
    asm("{ .reg .u64 t; cvta.to.shared.u64 t, %1; cvt.u32.u64 %0, t; }"
        : "=r"(a) : "l"(p));
    return a;
}
__device__ __forceinline__ uint32_t bf16x2_pack(float hi_elem, float lo_elem) {
    uint32_t r;
    asm("cvt.rn.bf16x2.f32 %0, %1, %2;" : "=r"(r) : "f"(hi_elem), "f"(lo_elem));
    return r;
}
__device__ __forceinline__ void mma_bf16(float* d, const uint32_t* a, const uint32_t* b) {
    asm volatile(
        "mma.sync.aligned.m16n8k16.row.col.f32.bf16.bf16.f32 "
        "{%0,%1,%2,%3}, {%4,%5,%6,%7}, {%8,%9}, {%0,%1,%2,%3};"
        : "+f"(d[0]), "+f"(d[1]), "+f"(d[2]), "+f"(d[3])
        : "r"(a[0]), "r"(a[1]), "r"(a[2]), "r"(a[3]), "r"(b[0]), "r"(b[1]));
}
#define LDSM4(r0, r1, r2, r3, addr) \
    asm volatile("ldmatrix.sync.aligned.m8n8.x4.shared.b16 {%0,%1,%2,%3}, [%4];" \
        : "=r"(r0), "=r"(r1), "=r"(r2), "=r"(r3) : "r"(addr))

// ==================== paired bf16-split mma GEMM (R14, measured best) ======
struct GPair {
    const float* A1; const float* B1;
    const float* A2; const float* B2;
    float* C; float* C2;
    const float* bias;
    int K1, lda1, ldb1, K2, lda2, ldb2, ldc, ldc2, do_tanh, N;
};

#define TW 36
#define ROWB 144
#define ABUF_WORDS (128 * TW)
#define BUF_WORDS  (2 * ABUF_WORDS)
#define GEMM_SMEM  (2 * BUF_WORDS * 4)   // 73728 bytes

__global__ void __launch_bounds__(256, 1) gemm_tc_kernel(GPair g0, GPair g1)
{
    extern __shared__ uint32_t sm[];
    const GPair g = blockIdx.z ? g1 : g0;
    const int tid = threadIdx.x;
    const int wid = tid >> 5, lane = tid & 31;
    const int wm = wid >> 1, wn = wid & 1;
    const int m0 = blockIdx.y * 128, n0 = blockIdx.x * 128;
    const uint32_t smem_base = smem_u32(sm);

    const int nc1 = g.K1 >> 5;
    const int nc  = nc1 + (g.K2 >> 5);

    float acc[2][8][4];
#pragma unroll
    for (int i = 0; i < 2; i++)
#pragma unroll
        for (int j = 0; j < 8; j++)
#pragma unroll
            for (int c = 0; c < 4; c++) acc[i][j][c] = 0.f;

    float4 pa[4], pb[4];

    auto ldreg = [&](int kc) {
        const float *A, *B;
        int lda, ldb, k0;
        if (kc < nc1) { A = g.A1; B = g.B1; lda = g.lda1; ldb = g.ldb1; k0 = kc << 5; }
        else          { A = g.A2; B = g.B2; lda = g.lda2; ldb = g.ldb2; k0 = (kc - nc1) << 5; }
#pragma unroll
        for (int i = 0; i < 4; i++) {
            const int idx = tid + 256 * i, row = idx >> 3, q = idx & 7;
            pa[i] = *(const float4*)(A + (size_t)(m0 + row) * lda + k0 + q * 4);
            int rb = n0 + row;
            if (rb >= g.N) rb = g.N - 1;
            pb[i] = *(const float4*)(B + (size_t)rb * ldb + k0 + q * 4);
        }
    };

    auto split_store = [&](int buf) {
        uint32_t* Ab = sm + buf * BUF_WORDS;
        uint32_t* Bb = Ab + ABUF_WORDS;
#pragma unroll
        for (int i = 0; i < 4; i++) {
            const int idx = tid + 256 * i, row = idx >> 3, q = idx & 7;
            {
                const float4 v = pa[i];
                const uint32_t hA = bf16x2_pack(v.y, v.x);
                const uint32_t hB = bf16x2_pack(v.w, v.z);
                const float l0 = v.x - __uint_as_float(hA << 16);
                const float l1 = v.y - __uint_as_float(hA & 0xFFFF0000u);
                const float l2 = v.z - __uint_as_float(hB << 16);
                const float l3 = v.w - __uint_as_float(hB & 0xFFFF0000u);
                *(uint2*)(Ab + row * TW + q * 2)      = make_uint2(hA, hB);
                *(uint2*)(Ab + row * TW + 16 + q * 2) =
                    make_uint2(bf16x2_pack(l1, l0), bf16x2_pack(l3, l2));
            }
            {
                const float4 v = pb[i];
                const uint32_t hA = bf16x2_pack(v.y, v.x);
                const uint32_t hB = bf16x2_pack(v.w, v.z);
                const float l0 = v.x - __uint_as_float(hA << 16);
                const float l1 = v.y - __uint_as_float(hA & 0xFFFF0000u);
                const float l2 = v.z - __uint_as_float(hB << 16);
                const float l3 = v.w - __uint_as_float(hB & 0xFFFF0000u);
                *(uint2*)(Bb + row * TW + q * 2)      = make_uint2(hA, hB);
                *(uint2*)(Bb + row * TW + 16 + q * 2) =
                    make_uint2(bf16x2_pack(l1, l0), bf16x2_pack(l3, l2));
            }
        }
    };

    ldreg(0);
    split_store(0);
    __syncthreads();

    const uint32_t aLaneOff =
        (uint32_t)(wm * 32 + (lane & 15)) * ROWB + (uint32_t)(lane >> 4) * 16u;
    const uint32_t bLaneOff =
        (uint32_t)(wn * 64 + ((lane >> 4) << 3) + (lane & 7)) * ROWB +
        (uint32_t)((lane >> 3) & 1) * 16u;

    for (int kc = 0; kc < nc; kc++) {
        const int buf = kc & 1;
        const bool hasNext = (kc + 1 < nc);
        if (hasNext) ldreg(kc + 1);

        const uint32_t bufB = smem_base + (uint32_t)buf * (BUF_WORDS * 4u);
        const uint32_t aB = bufB + aLaneOff;
        const uint32_t bB = bufB + (ABUF_WORDS * 4u) + bLaneOff;

#pragma unroll
        for (int ks = 0; ks < 2; ks++) {
            uint32_t ah[2][4], al[2][4];
#pragma unroll
            for (int mt = 0; mt < 2; mt++) {
                const uint32_t a_addr = aB + (uint32_t)mt * (16u * ROWB) + (uint32_t)ks * 32u;
                LDSM4(ah[mt][0], ah[mt][1], ah[mt][2], ah[mt][3], a_addr);
                LDSM4(al[mt][0], al[mt][1], al[mt][2], al[mt][3], a_addr + 64u);
            }
#pragma unroll
            for (int gq = 0; gq < 2; gq++) {
                uint32_t bh[4][2], bl[4][2];
#pragma unroll
                for (int p = 0; p < 2; p++) {
                    const uint32_t b_addr = bB + (uint32_t)gq * (32u * ROWB) +
                                            (uint32_t)p * (16u * ROWB) + (uint32_t)ks * 32u;
                    LDSM4(bh[2*p][0], bh[2*p][1], bh[2*p+1][0], bh[2*p+1][1], b_addr);
                    LDSM4(bl[2*p][0], bl[2*p][1], bl[2*p+1][0], bl[2*p+1][1], b_addr + 64u);
                }
#pragma unroll
                for (int mt = 0; mt < 2; mt++)
#pragma unroll
                    for (int nt = 0; nt < 4; nt++)
                        mma_bf16(acc[mt][gq * 4 + nt], ah[mt], bh[nt]);
#pragma unroll
                for (int mt = 0; mt < 2; mt++)
#pragma unroll
                    for (int nt = 0; nt < 4; nt++)
                        mma_bf16(acc[mt][gq * 4 + nt], ah[mt], bl[nt]);
#pragma unroll
                for (int mt = 0; mt < 2; mt++)
#pragma unroll
                    for (int nt = 0; nt < 4; nt++)
                        mma_bf16(acc[mt][gq * 4 + nt], al[mt], bh[nt]);
            }
        }
        if (hasNext) split_store(buf ^ 1);
        __syncthreads();
    }

    const int r_in = lane >> 2, c_in = 2 * (lane & 3);
#pragma unroll
    for (int mt = 0; mt < 2; mt++) {
#pragma unroll
        for (int nt = 0; nt < 8; nt++) {
            const int r0 = m0 + wm * 32 + mt * 16 + r_in;
            const int cc = n0 + wn * 64 + nt * 8 + c_in;
            if (cc >= g.N) continue;
            float v0 = acc[mt][nt][0], v1 = acc[mt][nt][1];
            float v2 = acc[mt][nt][2], v3 = acc[mt][nt][3];
            if (g.bias) {
                const float b0 = g.bias[cc], b1 = g.bias[cc + 1];
                v0 += b0; v1 += b1; v2 += b0; v3 += b1;
            }
            if (g.do_tanh) {
                v0 = tanhf(v0); v1 = tanhf(v1); v2 = tanhf(v2); v3 = tanhf(v3);
            }
            *(float2*)(g.C + (size_t)r0 * g.ldc + cc)       = make_float2(v0, v1);
            *(float2*)(g.C + (size_t)(r0 + 8) * g.ldc + cc) = make_float2(v2, v3);
            if (g.C2) {
                *(float2*)(g.C2 + (size_t)r0 * g.ldc2 + cc)       = make_float2(v0, v1);
                *(float2*)(g.C2 + (size_t)(r0 + 8) * g.ldc2 + cc) = make_float2(v2, v3);
            }
        }
    }
}

// ==================== object attention: 3-way NV-split partials ============
// blockIdx.x = set*1536 + b*3 + h; rows [h*12, h*12+12).
// Writes UNNORMALIZED acc + (m, d) per partial.
__global__ __launch_bounds__(256) void attn_obj_part_kernel(
    const float* __restrict__ denseObj, const float* __restrict__ feature,
    const float* __restrict__ tD, const float* __restrict__ tF,
    const int* __restrict__ omask,
    float* __restrict__ pacc, float* __restrict__ pmd)
{
    __shared__ float red[2][8];
    __shared__ int msk[12];
    const int pb = blockIdx.x;
    const int set = pb / 1536;
    const int rem = pb - set * 1536;
    const int b = rem / 3, h = rem - (rem / 3) * 3;
    const int r0 = h * 12;
    const float* feat   = set ? feature : denseObj;
    const float* target = set ? tF : tD;
    const int tid = threadIdx.x;
    const int wid = tid >> 5, lane = tid & 31;
    if (tid < 12) msk[tid] = set ? 0 : omask[b * NV + r0 + tid];

    const bool v2 = tid < (FEAT4 - 512);   // tid < 32
    const float4 z4 = make_float4(0.f, 0.f, 0.f, 0.f);
    const float4* tg4 = (const float4*)(target + (size_t)b * FEAT);
    float4 tg0 = tg4[tid], tg1 = tg4[tid + 256];
    float4 tg2 = v2 ? tg4[tid + 512] : z4;
    float4 ac0 = z4, ac1 = z4, ac2 = z4;

    const float4* f4 = (const float4*)(feat + ((size_t)b * NV + r0) * FEAT);
    float4 cu0 = f4[tid], cu1 = f4[tid + 256];
    float4 cu2 = v2 ? f4[tid + 512] : z4;

    float m_run = -3.0e38f, d_run = 0.f;
    __syncthreads();

#pragma unroll 1
    for (int s = 0; s < 12; s++) {
        float4 nx0 = cu0, nx1 = cu1, nx2 = cu2;
        if (s + 1 < 12) {
            const float4* fn = f4 + (size_t)(s + 1) * FEAT4;
            nx0 = fn[tid]; nx1 = fn[tid + 256];
            if (v2) nx2 = fn[tid + 512];
        }
        float p = cu0.x*tg0.x + cu0.y*tg0.y + cu0.z*tg0.z + cu0.w*tg0.w
                + cu1.x*tg1.x + cu1.y*tg1.y + cu1.z*tg1.z + cu1.w*tg1.w
                + cu2.x*tg2.x + cu2.y*tg2.y + cu2.z*tg2.z + cu2.w*tg2.w;
#pragma unroll
        for (int o = 16; o > 0; o >>= 1) p += __shfl_xor_sync(~0u, p, o);
        if (lane == 0) red[s & 1][wid] = p;
        __syncthreads();
        float l = ((red[s&1][0] + red[s&1][1]) + (red[s&1][2] + red[s&1][3]))
                + ((red[s&1][4] + red[s&1][5]) + (red[s&1][6] + red[s&1][7]));
        if (msk[s]) l = -1e30f;
        const float nm = fmaxf(m_run, l);
        const float sc = __expf(m_run - nm);
        const float w  = __expf(l - nm);
        m_run = nm;
        d_run = d_run * sc + w;
        ac0.x = ac0.x*sc + w*cu0.x; ac0.y = ac0.y*sc + w*cu0.y;
        ac0.z = ac0.z*sc + w*cu0.z; ac0.w = ac0.w*sc + w*cu0.w;
        ac1.x = ac1.x*sc + w*cu1.x; ac1.y = ac1.y*sc + w*cu1.y;
        ac1.z = ac1.z*sc + w*cu1.z; ac1.w = ac1.w*sc + w*cu1.w;
        ac2.x = ac2.x*sc + w*cu2.x; ac2.y = ac2.y*sc + w*cu2.y;
        ac2.z = ac2.z*sc + w*cu2.z; ac2.w = ac2.w*sc + w*cu2.w;
        cu0 = nx0; cu1 = nx1; cu2 = nx2;
    }
    float4* op = (float4*)(pacc + (size_t)pb * FEAT);
    op[tid]       = ac0;
    op[tid + 256] = ac1;
    if (v2) op[tid + 512] = ac2;
    if (tid == 0) { pmd[2 * pb] = m_run; pmd[2 * pb + 1] = d_run; }
}

// merge: blockIdx.x = set*512 + b. out = sum_i acc_i * w_i / D.
__global__ __launch_bounds__(256) void attn_obj_merge_kernel(
    const float* __restrict__ pacc, const float* __restrict__ pmd,
    float* __restrict__ outD, float* __restrict__ outF, int out_ld)
{
    __shared__ float wsh[4];
    const int mb = blockIdx.x;
    const int set = mb >> 9, b = mb & 511;
    const int base = set * 1536 + b * 3;
    const int tid = threadIdx.x;
    if (tid == 0) {
        const float m0 = pmd[2*base],     d0 = pmd[2*base + 1];
        const float m1 = pmd[2*(base+1)], d1 = pmd[2*(base+1) + 1];
        const float m2 = pmd[2*(base+2)], d2 = pmd[2*(base+2) + 1];
        const float M = fmaxf(m0, fmaxf(m1, m2));
        const float w0 = __expf(m0 - M), w1 = __expf(m1 - M), w2 = __expf(m2 - M);
        const float D = d0*w0 + d1*w1 + d2*w2;
        wsh[0] = w0; wsh[1] = w1; wsh[2] = w2; wsh[3] = 1.f / D;
    }
    __syncthreads();
    const float w0 = wsh[0], w1 = wsh[1], w2 = wsh[2], di = wsh[3];
    const float4* a0 = (const float4*)(pacc + (size_t)base * FEAT);
    const float4* a1 = (const float4*)(pacc + (size_t)(base + 1) * FEAT);
    const float4* a2 = (const float4*)(pacc + (size_t)(base + 2) * FEAT);
    float* outp = (set ? outF : outD) + (size_t)b * out_ld;
    for (int j = tid; j < FEAT4; j += 256) {
        const float4 x0 = a0[j], x1 = a1[j], x2 = a2[j];
        float4 r;
        r.x = (x0.x*w0 + x1.x*w1 + x2.x*w2) * di;
        r.y = (x0.y*w0 + x1.y*w1 + x2.y*w2) * di;
        r.z = (x0.z*w0 + x1.z*w1 + x2.z*w2) * di;
        r.w = (x0.w*w0 + x1.w*w1 + x2.w*w2) * di;
        *(float4*)(outp + j * 4) = r;
    }
}

// ==================== fused ctx attention (v + o) ====================
#define CTX_SMEM (SEQ * HID * 4)
__global__ __launch_bounds__(256) void attn_ctx_kernel(
    const float* __restrict__ ctx, const float* __restrict__ tgtV,
    const float* __restrict__ tgtO, const int* __restrict__ mask,
    float* __restrict__ outV, float* __restrict__ outO, int out_ld)
{
    extern __shared__ float cs[];
    __shared__ float tv[HID], tw[HID];
    __shared__ float lgv[SEQ], lgo[SEQ], pv[SEQ], po[SEQ];
    __shared__ float sdv, sdo;
    const int b = blockIdx.x, tid = threadIdx.x;
    const int wid = tid >> 5, lane = tid & 31;

    const float4* src = (const float4*)(ctx + (size_t)b * SEQ * HID);
    float4* cs4 = (float4*)cs;
    for (int i = tid; i < SEQ * HID / 4; i += 256) cs4[i] = src[i];
    for (int j = tid; j < HID; j += 256) {
        tv[j] = tgtV[(size_t)b * HID + j];
        tw[j] = tgtO[(size_t)b * HID + j];
    }
    __syncthreads();

    for (int s = wid; s < SEQ; s += 8) {
        const float* r = cs + s * HID;
        float av = 0.f, ao = 0.f;
#pragma unroll 4
        for (int j = lane; j < HID; j += 32) {
            const float x = r[j];
            av = fmaf(x, tv[j], av);
            ao = fmaf(x, tw[j], ao);
        }
#pragma unroll
        for (int o = 16; o > 0; o >>= 1) {
            av += __shfl_xor_sync(~0u, av, o);
            ao += __shfl_xor_sync(~0u, ao, o);
        }
        if (lane == 0) {
            const int mk = mask[b * SEQ + s];
            lgv[s] = mk ? -1e30f : av;
            lgo[s] = mk ? -1e30f : ao;
        }
    }
    __syncthreads();
    if (tid == 0) {
        float m = -3.0e38f;
        for (int s = 0; s < SEQ; s++) m = fmaxf(m, lgv[s]);
        float d = 0.f;
        for (int s = 0; s < SEQ; s++) { const float e = __expf(lgv[s] - m); pv[s] = e; d += e; }
        sdv = d;
    }
    if (tid == 32) {
        float m = -3.0e38f;
        for (int s = 0; s < SEQ; s++) m = fmaxf(m, lgo[s]);
        float d = 0.f;
        for (int s = 0; s < SEQ; s++) { const float e = __expf(lgo[s] - m); po[s] = e; d += e; }
        sdo = d;
    }
    __syncthreads();
    const float dv = 1.f / sdv, dw = 1.f / sdo;
    for (int j = tid; j < HID; j += 256) {
        float sv = 0.f, so = 0.f;
#pragma unroll 4
        for (int s = 0; s < SEQ; s++) {
            const float x = cs[s * HID + j];
            sv = fmaf(pv[s], x, sv);
            so = fmaf(po[s], x, so);
        }
        outV[(size_t)b * out_ld + j] = sv * dv;
        outO[(size_t)b * out_ld + j] = so * dw;
    }
}

// ==================== combined LSTM cells (v + o) ====================
__global__ __launch_bounds__(256) void lstm2_kernel(
    const float* __restrict__ gV, const float* __restrict__ gO,
    const float* __restrict__ bihV, const float* __restrict__ bhhV,
    const float* __restrict__ bihO, const float* __restrict__ bhhO,
    const float* __restrict__ c0,
    float* __restrict__ hV, float* __restrict__ cV, float* __restrict__ h2V,
    float* __restrict__ hO, float* __restrict__ cO, float* __restrict__ h2O,
    int ld2)
{
    const int gidx = blockIdx.x * 256 + threadIdx.x;
    const int set = gidx >> 18;
    const int idx = gidx & 262143;
    const int b = idx >> 9, j = idx & 511;
    const float* gates = set ? gO : gV;
    const float* bih = set ? bihO : bihV;
    const float* bhh = set ? bhhO : bhhV;
    float* h_out  = set ? hO : hV;
    float* c_out  = set ? cO : cV;
    float* h_out2 = set ? h2O : h2V;
    const float* gr = gates + (size_t)b * GATES;
    const float gi = gr[j]        + bih[j]        + bhh[j];
    const float gf = gr[512 + j]  + bih[512 + j]  + bhh[512 + j];
    const float gg = gr[1024 + j] + bih[1024 + j] + bhh[1024 + j];
    const float go = gr[1536 + j] + bih[1536 + j] + bhh[1536 + j];
    const float si = 1.f / (1.f + expf(-gi));
    const float sf = 1.f / (1.f + expf(-gf));
    const float so = 1.f / (1.f + expf(-go));
    const float c1 = sf * c0[idx] + si * tanhf(gg);
    const float h1 = so * tanhf(c1);
    h_out[idx] = h1;
    c_out[idx] = c1;
    h_out2[(size_t)b * ld2 + j] = h1;
}

// ==================== candidate logits ====================
__global__ __launch_bounds__(256) void cand_logits_kernel(
    const float* __restrict__ cand, const float* __restrict__ T,
    float* __restrict__ out)
{
    const int w = (blockIdx.x * 256 + threadIdx.x) >> 5;
    const int lane = threadIdx.x & 31;
    const int b = w >> 4, c = w & 15;
    const float4* cr = (const float4*)(cand + ((size_t)b * NC + c) * FEAT);
    const float4* tr = (const float4*)(T + (size_t)b * FEAT);
    float acc = 0.f;
    for (int j = lane; j < FEAT4; j += 32) {
        const float4 a = cr[j], t = tr[j];
        acc += a.x*t.x + a.y*t.y + a.z*t.z + a.w*t.w;
    }
#pragma unroll
    for (int o = 16; o > 0; o >>= 1) acc += __shfl_xor_sync(~0u, acc, o);
    if (lane == 0) out[w] = acc;
}

// ==================== host ====================
static GPair mk(const float* A1, const float* B1, int K1, int lda1, int ldb1,
                float* C, int ldc, int N,
                const float* A2 = nullptr, const float* B2 = nullptr,
                int K2 = 0, int lda2 = 0, int ldb2 = 0,
                float* C2 = nullptr, int ldc2 = 0,
                const float* bias = nullptr, int do_tanh = 0)
{
    GPair g;
    g.A1 = A1; g.B1 = B1; g.A2 = A2; g.B2 = B2;
    g.C = C; g.C2 = C2; g.bias = bias;
    g.K1 = K1; g.lda1 = lda1; g.ldb1 = ldb1;
    g.K2 = K2; g.lda2 = lda2; g.ldb2 = ldb2;
    g.ldc = ldc; g.ldc2 = ldc2; g.do_tanh = do_tanh; g.N = N;
    return g;
}

extern "C" void kernel_launch(void* const* d_in, const int* in_sizes, int n_in,
                              void* d_out, int out_size)
{
    const float* action    = (const float*)d_in[0];
    const float* cand_feat = (const float*)d_in[1];
    const float* prev_h1_v = (const float*)d_in[2];
    const float* prev_h1_o = (const float*)d_in[3];
    const float* c_0_o     = (const float*)d_in[5];
    const float* ctx       = (const float*)d_in[6];
    const int*   ctx_mask  = (const int*)d_in[7];
    const float* feature   = (const float*)d_in[8];
    const float* denseObj  = (const float*)d_in[9];
    const int*   obj_mask  = (const int*)d_in[10];
    const float* W_emb     = (const float*)d_in[11];
    const float* b_emb     = (const float*)d_in[12];
    const float* Wih_v     = (const float*)d_in[13];
    const float* Whh_v     = (const float*)d_in[14];
    const float* bih_v     = (const float*)d_in[15];
    const float* bhh_v     = (const float*)d_in[16];
    const float* Wih_o     = (const float*)d_in[17];
    const float* Whh_o     = (const float*)d_in[18];
    const float* bih_o     = (const float*)d_in[19];
    const float* bhh_o     = (const float*)d_in[20];
    const float* Wq_feat   = (const float*)d_in[21];
    const float* Wq_dense  = (const float*)d_in[22];
    const float* Wq_av     = (const float*)d_in[23];
    const float* Wo_av     = (const float*)d_in[24];
    const float* Wq_ao     = (const float*)d_in[25];
    const float* Wo_ao     = (const float*)d_in[26];
    const float* Wq_cand   = (const float*)d_in[27];
    float* out = (float*)d_out;

    cudaFuncSetAttribute(gemm_tc_kernel,
                         cudaFuncAttributeMaxDynamicSharedMemorySize, GEMM_SMEM);
    cudaFuncSetAttribute(attn_ctx_kernel,
                         cudaFuncAttributeMaxDynamicSharedMemorySize, CTX_SMEM);

    float* scr = nullptr;
    cudaGetSymbolAddress((void**)&scr, g_scratch);

    // 1) action embeds: tanh(action @ W_emb^T + b) -> Xv[:, :64] and Xo[:, :64]
    {
        GPair g = mk(action, W_emb, ANGLE, ANGLE, ANGLE, scr + O_XV, INDIM, EMB,
                     nullptr, nullptr, 0, 0, 0, scr + O_XO, INDIM, b_emb, 1);
        gemm_tc_kernel<<<dim3(1, 4, 1), 256, GEMM_SMEM>>>(g, g);
    }

    // 2) attention targets (dense + feat), paired
    {
        GPair gd = mk(prev_h1_o, Wq_dense, HID, HID, HID, scr + O_TDENSE, FEAT, FEAT);
        GPair gf = mk(prev_h1_v, Wq_feat,  HID, HID, HID, scr + O_TFEAT,  FEAT, FEAT);
        gemm_tc_kernel<<<dim3(FEAT / 128, 4, 2), 256, GEMM_SMEM>>>(gd, gf);
    }

    // 3) object/feature attention, 3-way NV split + merge -> Xo[:,64:], Xv[:,64:]
    attn_obj_part_kernel<<<3072, 256>>>(denseObj, feature,
                                        scr + O_TDENSE, scr + O_TFEAT, obj_mask,
                                        scr + P_ACC, scr + P_MD);
    attn_obj_merge_kernel<<<1024, 256>>>(scr + P_ACC, scr + P_MD,
                                         scr + O_XO + EMB, scr + O_XV + EMB, INDIM);

    // 4) LSTM gates: fused input + recurrent, v & o paired
    {
        GPair gv = mk(scr + O_XV, Wih_v, INDIM, INDIM, INDIM, scr + O_GV, GATES, GATES,
                      prev_h1_v, Whh_v, HID, HID, HID);
        GPair go = mk(scr + O_XO, Wih_o, INDIM, INDIM, INDIM, scr + O_GO, GATES, GATES,
                      prev_h1_o, Whh_o, HID, HID, HID);
        gemm_tc_kernel<<<dim3(GATES / 128, 4, 2), 256, GEMM_SMEM>>>(gv, go);
    }

    // 5) LSTM cells (both use c_0_o per reference)
    lstm2_kernel<<<2 * (BATCH * HID) / 256, 256>>>(
        scr + O_GV, scr + O_GO, bih_v, bhh_v, bih_o, bhh_o, c_0_o,
        out + OFF_H1V, out + OFF_C1V, scr + O_HCV + HID,
        out + OFF_H1O, out + OFF_C1O, scr + O_HCO + HID, 2 * HID);

    // 6) ctx attention targets, paired
    {
        GPair gv = mk(out + OFF_H1V, Wq_av, HID, HID, HID, scr + O_TAVV, HID, HID);
        GPair go = mk(out + OFF_H1O, Wq_ao, HID, HID, HID, scr + O_TAVO, HID, HID);
        gemm_tc_kernel<<<dim3(HID / 128, 4, 2), 256, GEMM_SMEM>>>(gv, go);
    }

    // 7) fused masked ctx attention (v + o)
    attn_ctx_kernel<<<BATCH, 256, CTX_SMEM>>>(
        ctx, scr + O_TAVV, scr + O_TAVO, ctx_mask,
        scr + O_HCV, scr + O_HCO, 2 * HID);

    // 8) h_tilde = tanh([wctx, h1] @ Wo^T), paired, dual-write
    {
        GPair gv = mk(scr + O_HCV, Wo_av, 2 * HID, 2 * HID, 2 * HID,
                      out + OFF_HTV, HID, HID, nullptr, nullptr, 0, 0, 0,
                      scr + O_HC2, 2 * HID, nullptr, 1);
        GPair go = mk(scr + O_HCO, Wo_ao, 2 * HID, 2 * HID, 2 * HID,
                      out + OFF_HTO, HID, HID, nullptr, nullptr, 0, 0, 0,
                      scr + O_HC2 + HID, 2 * HID, nullptr, 1);
        gemm_tc_kernel<<<dim3(HID / 128, 4, 2), 256, GEMM_SMEM>>>(gv, go);
    }

    // 9) candidate target + logits
    {
        GPair g = mk(scr + O_HC2, Wq_cand, 2 * HID, 2 * HID, 2 * HID,
                     scr + O_TCAND, FEAT, FEAT);
        gemm_tc_kernel<<<dim3(FEAT / 128, 4, 1), 256, GEMM_SMEM>>>(g, g);
    }
    cand_logits_kernel<<<(BATCH * NC * 32) / 256, 256>>>(
        cand_feat, scr + O_TCAND, out + OFF_LOGIT);
}

// round 16
// speedup vs baseline: 1.1233x; 1.1233x over previous
#include <cuda_runtime.h>
#include <math.h>
#include <stdint.h>

#define BATCH 512
#define SEQ   80
#define NV    36
#define NC    16
#define ANGLE 128
#define EMB   64
#define HID   512
#define FEAT  2176
#define INDIM 2240
#define GATES 2048
#define FEAT4 544

// ---------------- scratch ----------------
#define O_TDENSE 0u
#define O_TFEAT  1114112u
#define O_XV     2228224u
#define O_XO     3375104u
#define O_GV     4521984u
#define O_GO     5570560u
#define O_HCV    6619136u
#define O_HCO    7143424u
#define O_TAVV   7667712u
#define O_TAVO   7929856u
#define O_HC2    8192000u
#define O_TCAND  8716288u
#define SCRATCH_FLOATS 9830400u
__device__ float g_scratch[SCRATCH_FLOATS];

#define OFF_H1V   0u
#define OFF_H1O   262144u
#define OFF_C1V   524288u
#define OFF_C1O   786432u
#define OFF_LOGIT 1048576u
#define OFF_HTV   1056768u
#define OFF_HTO   1318912u

// ==================== helpers ====================
__device__ __forceinline__ uint32_t smem_u32(const void* p) {
    uint32_t a;
    asm("{ .reg .u64 t; cvta.to.shared.u64 t, %1; cvt.u32.u64 %0, t; }"
        : "=r"(a) : "l"(p));
    return a;
}
__device__ __forceinline__ uint32_t bf16x2_pack(float hi_elem, float lo_elem) {
    uint32_t r;
    asm("cvt.rn.bf16x2.f32 %0, %1, %2;" : "=r"(r) : "f"(hi_elem), "f"(lo_elem));
    return r;
}
__device__ __forceinline__ void mma_bf16(float* d, const uint32_t* a, const uint32_t* b) {
    asm volatile(
        "mma.sync.aligned.m16n8k16.row.col.f32.bf16.bf16.f32 "
        "{%0,%1,%2,%3}, {%4,%5,%6,%7}, {%8,%9}, {%0,%1,%2,%3};"
        : "+f"(d[0]), "+f"(d[1]), "+f"(d[2]), "+f"(d[3])
        : "r"(a[0]), "r"(a[1]), "r"(a[2]), "r"(a[3]), "r"(b[0]), "r"(b[1]));
}
#define LDSM4(r0, r1, r2, r3, addr) \
    asm volatile("ldmatrix.sync.aligned.m8n8.x4.shared.b16 {%0,%1,%2,%3}, [%4];" \
        : "=r"(r0), "=r"(r1), "=r"(r2), "=r"(r3) : "r"(addr))

struct GPair {
    const float* A1; const float* B1;
    const float* A2; const float* B2;
    float* C; float* C2;
    const float* bias;
    int K1, lda1, ldb1, K2, lda2, ldb2, ldc, ldc2, do_tanh, N;
};

#define TW 36
#define ROWB 144

// epilogue shared by both variants (per-warp-tile 32x64, acc[2][8][4])
__device__ __forceinline__ void gemm_epilogue(
    const GPair& g, float acc[2][8][4], int m0, int n0, int wm, int wn, int lane)
{
    const int r_in = lane >> 2, c_in = 2 * (lane & 3);
#pragma unroll
    for (int mt = 0; mt < 2; mt++) {
#pragma unroll
        for (int nt = 0; nt < 8; nt++) {
            const int r0 = m0 + wm * 32 + mt * 16 + r_in;
            const int cc = n0 + wn * 64 + nt * 8 + c_in;
            if (cc >= g.N) continue;
            float v0 = acc[mt][nt][0], v1 = acc[mt][nt][1];
            float v2 = acc[mt][nt][2], v3 = acc[mt][nt][3];
            if (g.bias) {
                const float b0 = g.bias[cc], b1 = g.bias[cc + 1];
                v0 += b0; v1 += b1; v2 += b0; v3 += b1;
            }
            if (g.do_tanh) {
                v0 = tanhf(v0); v1 = tanhf(v1); v2 = tanhf(v2); v3 = tanhf(v3);
            }
            *(float2*)(g.C + (size_t)r0 * g.ldc + cc)       = make_float2(v0, v1);
            *(float2*)(g.C + (size_t)(r0 + 8) * g.ldc + cc) = make_float2(v2, v3);
            if (g.C2) {
                *(float2*)(g.C2 + (size_t)r0 * g.ldc2 + cc)       = make_float2(v0, v1);
                *(float2*)(g.C2 + (size_t)(r0 + 8) * g.ldc2 + cc) = make_float2(v2, v3);
            }
        }
    }
}

// split one float4 into hi/lo bf16x2 pairs and store
__device__ __forceinline__ void split_store_f4(uint32_t* base_hi, const float4 v) {
    const uint32_t hA = bf16x2_pack(v.y, v.x);
    const uint32_t hB = bf16x2_pack(v.w, v.z);
    const float l0 = v.x - __uint_as_float(hA << 16);
    const float l1 = v.y - __uint_as_float(hA & 0xFFFF0000u);
    const float l2 = v.z - __uint_as_float(hB << 16);
    const float l3 = v.w - __uint_as_float(hB & 0xFFFF0000u);
    *(uint2*)(base_hi)      = make_uint2(hA, hB);
    *(uint2*)(base_hi + 16) = make_uint2(bf16x2_pack(l1, l0), bf16x2_pack(l3, l2));
}

// consume: load fragments with ldmatrix and issue 48 MMAs for one ks
__device__ __forceinline__ void mma_chunk_ks(
    float acc[2][8][4], uint32_t aB, uint32_t bB, int ks)
{
    uint32_t ah[2][4], al[2][4];
#pragma unroll
    for (int mt = 0; mt < 2; mt++) {
        const uint32_t a_addr = aB + (uint32_t)mt * (16u * ROWB) + (uint32_t)ks * 32u;
        LDSM4(ah[mt][0], ah[mt][1], ah[mt][2], ah[mt][3], a_addr);
        LDSM4(al[mt][0], al[mt][1], al[mt][2], al[mt][3], a_addr + 64u);
    }
#pragma unroll
    for (int gq = 0; gq < 2; gq++) {
        uint32_t bh[4][2], bl[4][2];
#pragma unroll
        for (int p = 0; p < 2; p++) {
            const uint32_t b_addr = bB + (uint32_t)gq * (32u * ROWB) +
                                    (uint32_t)p * (16u * ROWB) + (uint32_t)ks * 32u;
            LDSM4(bh[2*p][0], bh[2*p][1], bh[2*p+1][0], bh[2*p+1][1], b_addr);
            LDSM4(bl[2*p][0], bl[2*p][1], bl[2*p+1][0], bl[2*p+1][1], b_addr + 64u);
        }
#pragma unroll
        for (int mt = 0; mt < 2; mt++)
#pragma unroll
            for (int nt = 0; nt < 4; nt++)
                mma_bf16(acc[mt][gq * 4 + nt], ah[mt], bh[nt]);
#pragma unroll
        for (int mt = 0; mt < 2; mt++)
#pragma unroll
            for (int nt = 0; nt < 4; nt++)
                mma_bf16(acc[mt][gq * 4 + nt], ah[mt], bl[nt]);
#pragma unroll
        for (int mt = 0; mt < 2; mt++)
#pragma unroll
            for (int nt = 0; nt < 4; nt++)
                mma_bf16(acc[mt][gq * 4 + nt], al[mt], bh[nt]);
    }
}

// ==================== variant A: tile 128x128, 256 thr (R14 best) ==========
#define ABUF_WORDS (128 * TW)
#define BUF_WORDS  (2 * ABUF_WORDS)
#define GEMM_SMEM  (2 * BUF_WORDS * 4)   // 73728 bytes

__global__ void __launch_bounds__(256, 1) gemm_tc_kernel(GPair g0, GPair g1)
{
    extern __shared__ uint32_t sm[];
    const GPair g = blockIdx.z ? g1 : g0;
    const int tid = threadIdx.x;
    const int wid = tid >> 5, lane = tid & 31;
    const int wm = wid >> 1, wn = wid & 1;
    const int m0 = blockIdx.y * 128, n0 = blockIdx.x * 128;
    const uint32_t smem_base = smem_u32(sm);

    const int nc1 = g.K1 >> 5;
    const int nc  = nc1 + (g.K2 >> 5);

    float acc[2][8][4];
#pragma unroll
    for (int i = 0; i < 2; i++)
#pragma unroll
        for (int j = 0; j < 8; j++)
#pragma unroll
            for (int c = 0; c < 4; c++) acc[i][j][c] = 0.f;

    float4 pa[4], pb[4];

    auto ldreg = [&](int kc) {
        const float *A, *B;
        int lda, ldb, k0;
        if (kc < nc1) { A = g.A1; B = g.B1; lda = g.lda1; ldb = g.ldb1; k0 = kc << 5; }
        else          { A = g.A2; B = g.B2; lda = g.lda2; ldb = g.ldb2; k0 = (kc - nc1) << 5; }
#pragma unroll
        for (int i = 0; i < 4; i++) {
            const int idx = tid + 256 * i, row = idx >> 3, q = idx & 7;
            pa[i] = *(const float4*)(A + (size_t)(m0 + row) * lda + k0 + q * 4);
            int rb = n0 + row;
            if (rb >= g.N) rb = g.N - 1;
            pb[i] = *(const float4*)(B + (size_t)rb * ldb + k0 + q * 4);
        }
    };

    auto split_store = [&](int buf) {
        uint32_t* Ab = sm + buf * BUF_WORDS;
        uint32_t* Bb = Ab + ABUF_WORDS;
#pragma unroll
        for (int i = 0; i < 4; i++) {
            const int idx = tid + 256 * i, row = idx >> 3, q = idx & 7;
            split_store_f4(Ab + row * TW + q * 2, pa[i]);
            split_store_f4(Bb + row * TW + q * 2, pb[i]);
        }
    };

    ldreg(0);
    split_store(0);
    __syncthreads();

    const uint32_t aLaneOff =
        (uint32_t)(wm * 32 + (lane & 15)) * ROWB + (uint32_t)(lane >> 4) * 16u;
    const uint32_t bLaneOff =
        (uint32_t)(wn * 64 + ((lane >> 4) << 3) + (lane & 7)) * ROWB +
        (uint32_t)((lane >> 3) & 1) * 16u;

    for (int kc = 0; kc < nc; kc++) {
        const int buf = kc & 1;
        const bool hasNext = (kc + 1 < nc);
        if (hasNext) ldreg(kc + 1);

        const uint32_t bufB = smem_base + (uint32_t)buf * (BUF_WORDS * 4u);
        const uint32_t aB = bufB + aLaneOff;
        const uint32_t bB = bufB + (ABUF_WORDS * 4u) + bLaneOff;

        mma_chunk_ks(acc, aB, bB, 0);
        mma_chunk_ks(acc, aB, bB, 1);

        if (hasNext) split_store(buf ^ 1);
        __syncthreads();
    }
    gemm_epilogue(g, acc, m0, n0, wm, wn, lane);
}

// ==================== variant B: tile 64x128, 128 thr, 2 CTA/SM ============
// Same 32x64 warp tile / smem layout / numerics; M split for fill + overlap.
#define A64_WORDS (64 * TW)              // 2304
#define BUF64_WORDS (A64_WORDS + ABUF_WORDS)  // A(64 rows) + B(128 rows) = 6912
#define GEMM64_SMEM (2 * BUF64_WORDS * 4)     // 55296 bytes

__global__ void __launch_bounds__(128, 2) gemm64_tc_kernel(GPair g0, GPair g1)
{
    extern __shared__ uint32_t sm[];
    const GPair g = blockIdx.z ? g1 : g0;
    const int tid = threadIdx.x;
    const int wid = tid >> 5, lane = tid & 31;
    const int wm = wid >> 1, wn = wid & 1;   // 2x2 warps, warp tile 32x64
    const int m0 = blockIdx.y * 64, n0 = blockIdx.x * 128;
    const uint32_t smem_base = smem_u32(sm);

    const int nc1 = g.K1 >> 5;
    const int nc  = nc1 + (g.K2 >> 5);

    float acc[2][8][4];
#pragma unroll
    for (int i = 0; i < 2; i++)
#pragma unroll
        for (int j = 0; j < 8; j++)
#pragma unroll
            for (int c = 0; c < 4; c++) acc[i][j][c] = 0.f;

    float4 pa[4], pb[8];

    auto ldreg = [&](int kc) {
        const float *A, *B;
        int lda, ldb, k0;
        if (kc < nc1) { A = g.A1; B = g.B1; lda = g.lda1; ldb = g.ldb1; k0 = kc << 5; }
        else          { A = g.A2; B = g.B2; lda = g.lda2; ldb = g.ldb2; k0 = (kc - nc1) << 5; }
#pragma unroll
        for (int i = 0; i < 4; i++) {            // A: 64 rows x 8 = 512 f4
            const int idx = tid + 128 * i, row = idx >> 3, q = idx & 7;
            pa[i] = *(const float4*)(A + (size_t)(m0 + row) * lda + k0 + q * 4);
        }
#pragma unroll
        for (int i = 0; i < 8; i++) {            // B: 128 rows = 1024 f4
            const int idx = tid + 128 * i, row = idx >> 3, q = idx & 7;
            int rb = n0 + row;
            if (rb >= g.N) rb = g.N - 1;
            pb[i] = *(const float4*)(B + (size_t)rb * ldb + k0 + q * 4);
        }
    };

    auto split_store = [&](int buf) {
        uint32_t* Ab = sm + buf * BUF64_WORDS;
        uint32_t* Bb = Ab + A64_WORDS;
#pragma unroll
        for (int i = 0; i < 4; i++) {
            const int idx = tid + 128 * i, row = idx >> 3, q = idx & 7;
            split_store_f4(Ab + row * TW + q * 2, pa[i]);
        }
#pragma unroll
        for (int i = 0; i < 8; i++) {
            const int idx = tid + 128 * i, row = idx >> 3, q = idx & 7;
            split_store_f4(Bb + row * TW + q * 2, pb[i]);
        }
    };

    ldreg(0);
    split_store(0);
    __syncthreads();

    const uint32_t aLaneOff =
        (uint32_t)(wm * 32 + (lane & 15)) * ROWB + (uint32_t)(lane >> 4) * 16u;
    const uint32_t bLaneOff =
        (uint32_t)(wn * 64 + ((lane >> 4) << 3) + (lane & 7)) * ROWB +
        (uint32_t)((lane >> 3) & 1) * 16u;

    for (int kc = 0; kc < nc; kc++) {
        const int buf = kc & 1;
        const bool hasNext = (kc + 1 < nc);
        if (hasNext) ldreg(kc + 1);

        const uint32_t bufB = smem_base + (uint32_t)buf * (BUF64_WORDS * 4u);
        const uint32_t aB = bufB + aLaneOff;
        const uint32_t bB = bufB + (A64_WORDS * 4u) + bLaneOff;

        mma_chunk_ks(acc, aB, bB, 0);
        mma_chunk_ks(acc, aB, bB, 1);

        if (hasNext) split_store(buf ^ 1);
        __syncthreads();
    }
    gemm_epilogue(g, acc, m0, n0, wm, wn, lane);
}

// ==================== combined object attention: 2 rows per step (R14) =====
__global__ __launch_bounds__(256) void attn_obj2_kernel(
    const float* __restrict__ denseObj, const float* __restrict__ feature,
    const float* __restrict__ tD, const float* __restrict__ tF,
    const int* __restrict__ omask,
    float* __restrict__ outD, float* __restrict__ outF, int out_ld)
{
    __shared__ float red[2][2][8];
    __shared__ int msk[NV];
    const int set = blockIdx.x >> 9;
    const int b = blockIdx.x & 511;
    const float* feat   = set ? feature : denseObj;
    const float* target = set ? tF : tD;
    float* outp         = set ? outF : outD;
    const int tid = threadIdx.x;
    const int wid = tid >> 5, lane = tid & 31;
    if (tid < NV) msk[tid] = set ? 0 : omask[b * NV + tid];

    const bool v2 = tid < (FEAT4 - 512);
    const float4 z4 = make_float4(0.f, 0.f, 0.f, 0.f);
    const float4* tg4 = (const float4*)(target + (size_t)b * FEAT);
    float4 tg0 = tg4[tid], tg1 = tg4[tid + 256];
    float4 tg2 = v2 ? tg4[tid + 512] : z4;
    float4 ac0 = z4, ac1 = z4, ac2 = z4;

    const float4* f4 = (const float4*)(feat + (size_t)b * NV * FEAT);
    float4 cu0 = f4[tid], cu1 = f4[tid + 256];
    float4 cu2 = v2 ? f4[tid + 512] : z4;
    const float4* fr1 = f4 + FEAT4;
    float4 du0 = fr1[tid], du1 = fr1[tid + 256];
    float4 du2 = v2 ? fr1[tid + 512] : z4;
    const float4* fr2 = f4 + 2 * FEAT4;
    float4 px0 = fr2[tid], px1 = fr2[tid + 256];
    float4 px2 = v2 ? fr2[tid + 512] : z4;
    const float4* fr3 = f4 + 3 * FEAT4;
    float4 py0 = fr3[tid], py1 = fr3[tid + 256];
    float4 py2 = v2 ? fr3[tid + 512] : z4;

    float m_run = -3.0e38f, d_run = 0.f;
    __syncthreads();

#pragma unroll 1
    for (int sp = 0; sp < NV / 2; sp++) {
        const int s = 2 * sp;
        float4 n00 = px0, n01 = px1, n02 = px2;
        float4 n10 = py0, n11 = py1, n12 = py2;
        if (s + 5 < NV) {
            const float4* fa = f4 + (size_t)(s + 4) * FEAT4;
            const float4* fb = f4 + (size_t)(s + 5) * FEAT4;
            n00 = fa[tid]; n01 = fa[tid + 256];
            n10 = fb[tid]; n11 = fb[tid + 256];
            if (v2) { n02 = fa[tid + 512]; n12 = fb[tid + 512]; }
        }
        float p0 = cu0.x*tg0.x + cu0.y*tg0.y + cu0.z*tg0.z + cu0.w*tg0.w
                 + cu1.x*tg1.x + cu1.y*tg1.y + cu1.z*tg1.z + cu1.w*tg1.w
                 + cu2.x*tg2.x + cu2.y*tg2.y + cu2.z*tg2.z + cu2.w*tg2.w;
        float p1 = du0.x*tg0.x + du0.y*tg0.y + du0.z*tg0.z + du0.w*tg0.w
                 + du1.x*tg1.x + du1.y*tg1.y + du1.z*tg1.z + du1.w*tg1.w
                 + du2.x*tg2.x + du2.y*tg2.y + du2.z*tg2.z + du2.w*tg2.w;
#pragma unroll
        for (int o = 16; o > 0; o >>= 1) {
            p0 += __shfl_xor_sync(~0u, p0, o);
            p1 += __shfl_xor_sync(~0u, p1, o);
        }
        if (lane == 0) { red[sp & 1][0][wid] = p0; red[sp & 1][1][wid] = p1; }
        __syncthreads();
        float l0 = ((red[sp&1][0][0] + red[sp&1][0][1]) + (red[sp&1][0][2] + red[sp&1][0][3]))
                 + ((red[sp&1][0][4] + red[sp&1][0][5]) + (red[sp&1][0][6] + red[sp&1][0][7]));
        float l1 = ((red[sp&1][1][0] + red[sp&1][1][1]) + (red[sp&1][1][2] + red[sp&1][1][3]))
                 + ((red[sp&1][1][4] + red[sp&1][1][5]) + (red[sp&1][1][6] + red[sp&1][1][7]));
        if (msk[s])     l0 = -1e30f;
        if (msk[s + 1]) l1 = -1e30f;
        const float nm = fmaxf(m_run, fmaxf(l0, l1));
        const float sc = __expf(m_run - nm);
        const float w0 = __expf(l0 - nm);
        const float w1 = __expf(l1 - nm);
        m_run = nm;
        d_run = d_run * sc + w0 + w1;
        ac0.x = ac0.x*sc + w0*cu0.x + w1*du0.x;
        ac0.y = ac0.y*sc + w0*cu0.y + w1*du0.y;
        ac0.z = ac0.z*sc + w0*cu0.z + w1*du0.z;
        ac0.w = ac0.w*sc + w0*cu0.w + w1*du0.w;
        ac1.x = ac1.x*sc + w0*cu1.x + w1*du1.x;
        ac1.y = ac1.y*sc + w0*cu1.y + w1*du1.y;
        ac1.z = ac1.z*sc + w0*cu1.z + w1*du1.z;
        ac1.w = ac1.w*sc + w0*cu1.w + w1*du1.w;
        ac2.x = ac2.x*sc + w0*cu2.x + w1*du2.x;
        ac2.y = ac2.y*sc + w0*cu2.y + w1*du2.y;
        ac2.z = ac2.z*sc + w0*cu2.z + w1*du2.z;
        ac2.w = ac2.w*sc + w0*cu2.w + w1*du2.w;
        cu0 = px0; cu1 = px1; cu2 = px2;
        du0 = py0; du1 = py1; du2 = py2;
        px0 = n00; px1 = n01; px2 = n02;
        py0 = n10; py1 = n11; py2 = n12;
    }
    const float di = 1.f / d_run;
    float4* op = (float4*)(outp + (size_t)b * out_ld);
    op[tid]       = make_float4(ac0.x*di, ac0.y*di, ac0.z*di, ac0.w*di);
    op[tid + 256] = make_float4(ac1.x*di, ac1.y*di, ac1.z*di, ac1.w*di);
    if (v2)
        op[tid + 512] = make_float4(ac2.x*di, ac2.y*di, ac2.z*di, ac2.w*di);
}

// ==================== fused ctx attention (v + o) ====================
#define CTX_SMEM (SEQ * HID * 4)
__global__ __launch_bounds__(256) void attn_ctx_kernel(
    const float* __restrict__ ctx, const float* __restrict__ tgtV,
    const float* __restrict__ tgtO, const int* __restrict__ mask,
    float* __restrict__ outV, float* __restrict__ outO, int out_ld)
{
    extern __shared__ float cs[];
    __shared__ float tv[HID], tw[HID];
    __shared__ float lgv[SEQ], lgo[SEQ], pv[SEQ], po[SEQ];
    __shared__ float sdv, sdo;
    const int b = blockIdx.x, tid = threadIdx.x;
    const int wid = tid >> 5, lane = tid & 31;

    const float4* src = (const float4*)(ctx + (size_t)b * SEQ * HID);
    float4* cs4 = (float4*)cs;
    for (int i = tid; i < SEQ * HID / 4; i += 256) cs4[i] = src[i];
    for (int j = tid; j < HID; j += 256) {
        tv[j] = tgtV[(size_t)b * HID + j];
        tw[j] = tgtO[(size_t)b * HID + j];
    }
    __syncthreads();

    for (int s = wid; s < SEQ; s += 8) {
        const float* r = cs + s * HID;
        float av = 0.f, ao = 0.f;
#pragma unroll 4
        for (int j = lane; j < HID; j += 32) {
            const float x = r[j];
            av = fmaf(x, tv[j], av);
            ao = fmaf(x, tw[j], ao);
        }
#pragma unroll
        for (int o = 16; o > 0; o >>= 1) {
            av += __shfl_xor_sync(~0u, av, o);
            ao += __shfl_xor_sync(~0u, ao, o);
        }
        if (lane == 0) {
            const int mk = mask[b * SEQ + s];
            lgv[s] = mk ? -1e30f : av;
            lgo[s] = mk ? -1e30f : ao;
        }
    }
    __syncthreads();
    if (tid == 0) {
        float m = -3.0e38f;
        for (int s = 0; s < SEQ; s++) m = fmaxf(m, lgv[s]);
        float d = 0.f;
        for (int s = 0; s < SEQ; s++) { const float e = __expf(lgv[s] - m); pv[s] = e; d += e; }
        sdv = d;
    }
    if (tid == 32) {
        float m = -3.0e38f;
        for (int s = 0; s < SEQ; s++) m = fmaxf(m, lgo[s]);
        float d = 0.f;
        for (int s = 0; s < SEQ; s++) { const float e = __expf(lgo[s] - m); po[s] = e; d += e; }
        sdo = d;
    }
    __syncthreads();
    const float dv = 1.f / sdv, dw = 1.f / sdo;
    for (int j = tid; j < HID; j += 256) {
        float sv = 0.f, so = 0.f;
#pragma unroll 4
        for (int s = 0; s < SEQ; s++) {
            const float x = cs[s * HID + j];
            sv = fmaf(pv[s], x, sv);
            so = fmaf(po[s], x, so);
        }
        outV[(size_t)b * out_ld + j] = sv * dv;
        outO[(size_t)b * out_ld + j] = so * dw;
    }
}

// ==================== combined LSTM cells (v + o) ====================
__global__ __launch_bounds__(256) void lstm2_kernel(
    const float* __restrict__ gV, const float* __restrict__ gO,
    const float* __restrict__ bihV, const float* __restrict__ bhhV,
    const float* __restrict__ bihO, const float* __restrict__ bhhO,
    const float* __restrict__ c0,
    float* __restrict__ hV, float* __restrict__ cV, float* __restrict__ h2V,
    float* __restrict__ hO, float* __restrict__ cO, float* __restrict__ h2O,
    int ld2)
{
    const int gidx = blockIdx.x * 256 + threadIdx.x;
    const int set = gidx >> 18;
    const int idx = gidx & 262143;
    const int b = idx >> 9, j = idx & 511;
    const float* gates = set ? gO : gV;
    const float* bih = set ? bihO : bihV;
    const float* bhh = set ? bhhO : bhhV;
    float* h_out  = set ? hO : hV;
    float* c_out  = set ? cO : cV;
    float* h_out2 = set ? h2O : h2V;
    const float* gr = gates + (size_t)b * GATES;
    const float gi = gr[j]        + bih[j]        + bhh[j];
    const float gf = gr[512 + j]  + bih[512 + j]  + bhh[512 + j];
    const float gg = gr[1024 + j] + bih[1024 + j] + bhh[1024 + j];
    const float go = gr[1536 + j] + bih[1536 + j] + bhh[1536 + j];
    const float si = 1.f / (1.f + expf(-gi));
    const float sf = 1.f / (1.f + expf(-gf));
    const float so = 1.f / (1.f + expf(-go));
    const float c1 = sf * c0[idx] + si * tanhf(gg);
    const float h1 = so * tanhf(c1);
    h_out[idx] = h1;
    c_out[idx] = c1;
    h_out2[(size_t)b * ld2 + j] = h1;
}

// ==================== candidate logits ====================
__global__ __launch_bounds__(256) void cand_logits_kernel(
    const float* __restrict__ cand, const float* __restrict__ T,
    float* __restrict__ out)
{
    const int w = (blockIdx.x * 256 + threadIdx.x) >> 5;
    const int lane = threadIdx.x & 31;
    const int b = w >> 4, c = w & 15;
    const float4* cr = (const float4*)(cand + ((size_t)b * NC + c) * FEAT);
    const float4* tr = (const float4*)(T + (size_t)b * FEAT);
    float acc = 0.f;
    for (int j = lane; j < FEAT4; j += 32) {
        const float4 a = cr[j], t = tr[j];
        acc += a.x*t.x + a.y*t.y + a.z*t.z + a.w*t.w;
    }
#pragma unroll
    for (int o = 16; o > 0; o >>= 1) acc += __shfl_xor_sync(~0u, acc, o);
    if (lane == 0) out[w] = acc;
}

// ==================== host ====================
static GPair mk(const float* A1, const float* B1, int K1, int lda1, int ldb1,
                float* C, int ldc, int N,
                const float* A2 = nullptr, const float* B2 = nullptr,
                int K2 = 0, int lda2 = 0, int ldb2 = 0,
                float* C2 = nullptr, int ldc2 = 0,
                const float* bias = nullptr, int do_tanh = 0)
{
    GPair g;
    g.A1 = A1; g.B1 = B1; g.A2 = A2; g.B2 = B2;
    g.C = C; g.C2 = C2; g.bias = bias;
    g.K1 = K1; g.lda1 = lda1; g.ldb1 = ldb1;
    g.K2 = K2; g.lda2 = lda2; g.ldb2 = ldb2;
    g.ldc = ldc; g.ldc2 = ldc2; g.do_tanh = do_tanh; g.N = N;
    return g;
}

extern "C" void kernel_launch(void* const* d_in, const int* in_sizes, int n_in,
                              void* d_out, int out_size)
{
    const float* action    = (const float*)d_in[0];
    const float* cand_feat = (const float*)d_in[1];
    const float* prev_h1_v = (const float*)d_in[2];
    const float* prev_h1_o = (const float*)d_in[3];
    const float* c_0_o     = (const float*)d_in[5];
    const float* ctx       = (const float*)d_in[6];
    const int*   ctx_mask  = (const int*)d_in[7];
    const float* feature   = (const float*)d_in[8];
    const float* denseObj  = (const float*)d_in[9];
    const int*   obj_mask  = (const int*)d_in[10];
    const float* W_emb     = (const float*)d_in[11];
    const float* b_emb     = (const float*)d_in[12];
    const float* Wih_v     = (const float*)d_in[13];
    const float* Whh_v     = (const float*)d_in[14];
    const float* bih_v     = (const float*)d_in[15];
    const float* bhh_v     = (const float*)d_in[16];
    const float* Wih_o     = (const float*)d_in[17];
    const float* Whh_o     = (const float*)d_in[18];
    const float* bih_o     = (const float*)d_in[19];
    const float* bhh_o     = (const float*)d_in[20];
    const float* Wq_feat   = (const float*)d_in[21];
    const float* Wq_dense  = (const float*)d_in[22];
    const float* Wq_av     = (const float*)d_in[23];
    const float* Wo_av     = (const float*)d_in[24];
    const float* Wq_ao     = (const float*)d_in[25];
    const float* Wo_ao     = (const float*)d_in[26];
    const float* Wq_cand   = (const float*)d_in[27];
    float* out = (float*)d_out;

    cudaFuncSetAttribute(gemm_tc_kernel,
                         cudaFuncAttributeMaxDynamicSharedMemorySize, GEMM_SMEM);
    cudaFuncSetAttribute(gemm64_tc_kernel,
                         cudaFuncAttributeMaxDynamicSharedMemorySize, GEMM64_SMEM);
    cudaFuncSetAttribute(attn_ctx_kernel,
                         cudaFuncAttributeMaxDynamicSharedMemorySize, CTX_SMEM);

    float* scr = nullptr;
    cudaGetSymbolAddress((void**)&scr, g_scratch);

    // 1) action embeds (64-tile: 8 CTAs vs 4)
    {
        GPair g = mk(action, W_emb, ANGLE, ANGLE, ANGLE, scr + O_XV, INDIM, EMB,
                     nullptr, nullptr, 0, 0, 0, scr + O_XO, INDIM, b_emb, 1);
        gemm64_tc_kernel<<<dim3(1, 8, 1), 128, GEMM64_SMEM>>>(g, g);
    }

    // 2) attention targets (dense + feat), paired — fills chip, keep 128-tile
    {
        GPair gd = mk(prev_h1_o, Wq_dense, HID, HID, HID, scr + O_TDENSE, FEAT, FEAT);
        GPair gf = mk(prev_h1_v, Wq_feat,  HID, HID, HID, scr + O_TFEAT,  FEAT, FEAT);
        gemm_tc_kernel<<<dim3(FEAT / 128, 4, 2), 256, GEMM_SMEM>>>(gd, gf);
    }

    // 3) combined object/feature attention -> Xo[:,64:], Xv[:,64:]
    attn_obj2_kernel<<<2 * BATCH, 256>>>(denseObj, feature,
                                         scr + O_TDENSE, scr + O_TFEAT, obj_mask,
                                         scr + O_XO + EMB, scr + O_XV + EMB, INDIM);

    // 4) LSTM gates: fused input + recurrent, v & o paired — keep 128-tile
    {
        GPair gv = mk(scr + O_XV, Wih_v, INDIM, INDIM, INDIM, scr + O_GV, GATES, GATES,
                      prev_h1_v, Whh_v, HID, HID, HID);
        GPair go = mk(scr + O_XO, Wih_o, INDIM, INDIM, INDIM, scr + O_GO, GATES, GATES,
                      prev_h1_o, Whh_o, HID, HID, HID);
        gemm_tc_kernel<<<dim3(GATES / 128, 4, 2), 256, GEMM_SMEM>>>(gv, go);
    }

    // 5) LSTM cells (both use c_0_o per reference)
    lstm2_kernel<<<2 * (BATCH * HID) / 256, 256>>>(
        scr + O_GV, scr + O_GO, bih_v, bhh_v, bih_o, bhh_o, c_0_o,
        out + OFF_H1V, out + OFF_C1V, scr + O_HCV + HID,
        out + OFF_H1O, out + OFF_C1O, scr + O_HCO + HID, 2 * HID);

    // 6) ctx attention targets, paired — 64-tile (64 CTAs vs 32)
    {
        GPair gv = mk(out + OFF_H1V, Wq_av, HID, HID, HID, scr + O_TAVV, HID, HID);
        GPair go = mk(out + OFF_H1O, Wq_ao, HID, HID, HID, scr + O_TAVO, HID, HID);
        gemm64_tc_kernel<<<dim3(HID / 128, 8, 2), 128, GEMM64_SMEM>>>(gv, go);
    }

    // 7) fused masked ctx attention (v + o)
    attn_ctx_kernel<<<BATCH, 256, CTX_SMEM>>>(
        ctx, scr + O_TAVV, scr + O_TAVO, ctx_mask,
        scr + O_HCV, scr + O_HCO, 2 * HID);

    // 8) h_tilde, paired, dual-write — 64-tile (64 CTAs vs 32)
    {
        GPair gv = mk(scr + O_HCV, Wo_av, 2 * HID, 2 * HID, 2 * HID,
                      out + OFF_HTV, HID, HID, nullptr, nullptr, 0, 0, 0,
                      scr + O_HC2, 2 * HID, nullptr, 1);
        GPair go = mk(scr + O_HCO, Wo_ao, 2 * HID, 2 * HID, 2 * HID,
                      out + OFF_HTO, HID, HID, nullptr, nullptr, 0, 0, 0,
                      scr + O_HC2 + HID, 2 * HID, nullptr, 1);
        gemm64_tc_kernel<<<dim3(HID / 128, 8, 2), 128, GEMM64_SMEM>>>(gv, go);
    }

    // 9) candidate target + logits — 64-tile (136 CTAs vs 68)
    {
        GPair g = mk(scr + O_HC2, Wq_cand, 2 * HID, 2 * HID, 2 * HID,
                     scr + O_TCAND, FEAT, FEAT);
        gemm64_tc_kernel<<<dim3(FEAT / 128, 8, 1), 128, GEMM64_SMEM>>>(g, g);
    }
    cand_logits_kernel<<<(BATCH * NC * 32) / 256, 256>>>(
        cand_feat, scr + O_TCAND, out + OFF_LOGIT);
}